// round 1
// baseline (speedup 1.0000x reference)
#include <cuda_runtime.h>
#include <cstdint>

// ---------------------------------------------------------------------------
// Problem constants
//   em: (4,64,128,128)  dm: (4,128,64,64)  p: (4,1,64,64)
//   f = concat(em_path(16ch), dm_path(32ch)) -> (4,48,64,64), N=4096
//   Q,K,V: (4,128,4096);  att = sigmoid(Q^T K): (4,4096,4096)
//   o_v = V*p + V att^T ; out = prelu(bn(bt_w @ o_v)) : (4,64,64,64)
// ---------------------------------------------------------------------------
#define BATCH 4
#define NPIX  4096      // 64*64
#define CATT  128
#define EPS   1e-5f

// ---------------- device scratch (module-static, no runtime alloc) ---------
__device__ float g_tmp[BATCH * 16 * 128 * 128];          //  4 MB conv output
__device__ float g_f  [BATCH * 48 * NPIX];               //  3 MB fused features
__device__ float g_q  [BATCH * CATT * NPIX];             //  8 MB
__device__ float g_k  [BATCH * CATT * NPIX];             //  8 MB
__device__ float g_v  [BATCH * CATT * NPIX];             //  8 MB
__device__ float g_att[(size_t)BATCH * NPIX * NPIX];     // 268 MB attention
__device__ float g_ov [BATCH * CATT * NPIX];             //  8 MB

// ---------------- packed fp32x2 helpers (sm_100+) --------------------------
__device__ __forceinline__ unsigned long long pack2(float x, float y) {
    unsigned long long r;
    asm("mov.b64 %0, {%1, %2};" : "=l"(r) : "f"(x), "f"(y));
    return r;
}
__device__ __forceinline__ void unpack2(unsigned long long v, float& x, float& y) {
    asm("mov.b64 {%0, %1}, %2;" : "=f"(x), "=f"(y) : "l"(v));
}
__device__ __forceinline__ unsigned long long fma2(unsigned long long a,
                                                   unsigned long long b,
                                                   unsigned long long c) {
    unsigned long long d;
    asm("fma.rn.f32x2 %0, %1, %2, %3;" : "=l"(d) : "l"(a), "l"(b), "l"(c));
    return d;
}

// ---------------------------------------------------------------------------
// Kernel 1: conv3x3(em) + BN + PReLU  -> g_tmp (4,16,128,128)
// grid (8,8,4), block (16,16). Weights (16x64x9 = 36KB) cached in smem.
// ---------------------------------------------------------------------------
__global__ __launch_bounds__(256) void k_conv3(
    const float* __restrict__ em, const float* __restrict__ en_w,
    const float* __restrict__ en_b, const float* __restrict__ bn1_g,
    const float* __restrict__ bn1_b, const float* __restrict__ bn1_m,
    const float* __restrict__ bn1_v, const float* __restrict__ prelu1)
{
    __shared__ float ws[16 * 64 * 9];
    __shared__ float tile[18 * 18];
    const int tid = threadIdx.y * 16 + threadIdx.x;
    for (int idx = tid; idx < 16 * 64 * 9; idx += 256) ws[idx] = en_w[idx];

    const int b  = blockIdx.z;
    const int gx = blockIdx.x * 16 + threadIdx.x;
    const int gy = blockIdx.y * 16 + threadIdx.y;

    float acc[16];
#pragma unroll
    for (int o = 0; o < 16; o++) acc[o] = 0.f;

    const float* emb = em + (size_t)b * 64 * 128 * 128;

    for (int ci = 0; ci < 64; ci++) {
        __syncthreads();   // protects ws (1st iter) + tile reuse
        for (int idx = tid; idx < 18 * 18; idx += 256) {
            int r = idx / 18, c = idx % 18;
            int yy = (int)blockIdx.y * 16 + r - 1;
            int xx = (int)blockIdx.x * 16 + c - 1;
            float v = 0.f;
            if (yy >= 0 && yy < 128 && xx >= 0 && xx < 128)
                v = emb[(size_t)ci * 16384 + yy * 128 + xx];
            tile[idx] = v;
        }
        __syncthreads();
        float t[9];
#pragma unroll
        for (int kh = 0; kh < 3; kh++)
#pragma unroll
            for (int kw = 0; kw < 3; kw++)
                t[kh * 3 + kw] = tile[(threadIdx.y + kh) * 18 + threadIdx.x + kw];
        const float* w = ws + ci * 9;
#pragma unroll
        for (int o = 0; o < 16; o++) {
#pragma unroll
            for (int k = 0; k < 9; k++)
                acc[o] = fmaf(w[o * 576 + k], t[k], acc[o]);
        }
    }

    const float a = prelu1[0];
#pragma unroll
    for (int o = 0; o < 16; o++) {
        float y  = acc[o] + en_b[o];
        float sc = bn1_g[o] * rsqrtf(bn1_v[o] + EPS);
        y = (y - bn1_m[o]) * sc + bn1_b[o];
        y = (y >= 0.f) ? y : a * y;
        g_tmp[(((size_t)b * 16 + o) * 128 + gy) * 128 + gx] = y;
    }
}

// ---------------------------------------------------------------------------
// Kernel 2: build f (4,48,4096)
//   ch 0..15 : maxpool3x3 s2 p1 of g_tmp, then *dw_w + dw_b
//   ch 16..47: 1x1 conv of dm with de_w
// grid (16,48,4), block 256
// ---------------------------------------------------------------------------
__global__ __launch_bounds__(256) void k_build_f(
    const float* __restrict__ dm, const float* __restrict__ de_w,
    const float* __restrict__ de_b, const float* __restrict__ dw_w,
    const float* __restrict__ dw_b)
{
    const int b  = blockIdx.z;
    const int ch = blockIdx.y;
    const int i  = blockIdx.x * 256 + threadIdx.x;
    float out;
    if (ch < 16) {
        const int ph = i >> 6, pw = i & 63;
        float m = -1e30f;
        const float* tb = g_tmp + ((size_t)b * 16 + ch) * 16384;
#pragma unroll
        for (int dy = 0; dy < 3; dy++) {
            int y = 2 * ph - 1 + dy;
            if (y < 0 || y > 127) continue;
#pragma unroll
            for (int dx = 0; dx < 3; dx++) {
                int x = 2 * pw - 1 + dx;
                if (x < 0 || x > 127) continue;
                m = fmaxf(m, tb[y * 128 + x]);
            }
        }
        out = m * dw_w[ch] + dw_b[ch];
    } else {
        const int co = ch - 16;
        float accv = de_b[co];
        const float* dmb = dm + (size_t)b * 128 * NPIX + i;
        const float* w   = de_w + co * 128;
#pragma unroll 8
        for (int c = 0; c < 128; c++)
            accv = fmaf(__ldg(w + c), __ldg(dmb + (size_t)c * NPIX), accv);
        out = accv;
    }
    g_f[((size_t)b * 48 + ch) * NPIX + i] = out;
}

// ---------------------------------------------------------------------------
// Kernel 3: Q/K/V projections (each 128x48 @ 48x4096 per batch)
// grid (16,4), block 256. f column (48 floats) held in registers.
// ---------------------------------------------------------------------------
__global__ __launch_bounds__(256) void k_qkv(
    const float* __restrict__ q_w, const float* __restrict__ q_b,
    const float* __restrict__ k_w, const float* __restrict__ k_b,
    const float* __restrict__ v_w, const float* __restrict__ v_b)
{
    const int b = blockIdx.y;
    const int i = blockIdx.x * 256 + threadIdx.x;

    float fv[48];
#pragma unroll
    for (int k = 0; k < 48; k++)
        fv[k] = g_f[((size_t)b * 48 + k) * NPIX + i];

    const float* wsrc[3] = { q_w, k_w, v_w };
    const float* bsrc[3] = { q_b, k_b, v_b };
    float* dsts[3];
    dsts[0] = g_q + (size_t)b * CATT * NPIX;
    dsts[1] = g_k + (size_t)b * CATT * NPIX;
    dsts[2] = g_v + (size_t)b * CATT * NPIX;

    for (int pr = 0; pr < 3; pr++) {
        const float* w = wsrc[pr];
        const float* bb = bsrc[pr];
        float* dst = dsts[pr];
        for (int c = 0; c < 128; c++) {
            float accv = __ldg(bb + c);
            const float* wr = w + c * 48;
#pragma unroll
            for (int k = 0; k < 48; k++)
                accv = fmaf(__ldg(wr + k), fv[k], accv);
            dst[(size_t)c * NPIX + i] = accv;
        }
    }
}

// ---------------------------------------------------------------------------
// Kernel 4: energy GEMM + sigmoid.  att[b,i,j] = sigmoid(sum_c Q[c,i]K[c,j])
// 128x128 block tile, 8x8 microtile (f32x2-packed), K-chunk 16.
// grid (32 jt, 32 it, 4), block 256.
// ---------------------------------------------------------------------------
__global__ __launch_bounds__(256, 2) void k_energy()
{
    __shared__ __align__(16) float As[16][136];
    __shared__ __align__(16) float Bs[16][136];

    const int b  = blockIdx.z;
    const int i0 = blockIdx.y * 128;
    const int j0 = blockIdx.x * 128;
    const int tid = threadIdx.x;
    const int tx = tid & 15, ty = tid >> 4;

    const float* Qb = g_q + (size_t)b * CATT * NPIX;
    const float* Kb = g_k + (size_t)b * CATT * NPIX;

    const int lrow = tid >> 4;        // 0..15 (k)
    const int lcol = (tid & 15) * 8;  // 0..120

    unsigned long long acc[8][4];
#pragma unroll
    for (int r = 0; r < 8; r++)
#pragma unroll
        for (int q = 0; q < 4; q++) acc[r][q] = 0ull;

    for (int k0 = 0; k0 < 128; k0 += 16) {
        const float* ga = Qb + (size_t)(k0 + lrow) * NPIX + i0 + lcol;
        const float* gb = Kb + (size_t)(k0 + lrow) * NPIX + j0 + lcol;
        float4 a0 = *(const float4*)ga;
        float4 a1 = *(const float4*)(ga + 4);
        float4 b0 = *(const float4*)gb;
        float4 b1 = *(const float4*)(gb + 4);
        __syncthreads();
        *(float4*)&As[lrow][lcol]     = a0;
        *(float4*)&As[lrow][lcol + 4] = a1;
        *(float4*)&Bs[lrow][lcol]     = b0;
        *(float4*)&Bs[lrow][lcol + 4] = b1;
        __syncthreads();
#pragma unroll
        for (int kk = 0; kk < 16; kk++) {
            float4 av0 = *(const float4*)&As[kk][ty * 8];
            float4 av1 = *(const float4*)&As[kk][ty * 8 + 4];
            ulonglong2 bv0 = *(const ulonglong2*)&Bs[kk][tx * 8];
            ulonglong2 bv1 = *(const ulonglong2*)&Bs[kk][tx * 8 + 4];
            unsigned long long bp[4] = { bv0.x, bv0.y, bv1.x, bv1.y };
            float av[8] = { av0.x, av0.y, av0.z, av0.w,
                            av1.x, av1.y, av1.z, av1.w };
#pragma unroll
            for (int r = 0; r < 8; r++) {
                unsigned long long ap = pack2(av[r], av[r]);
#pragma unroll
                for (int q = 0; q < 4; q++)
                    acc[r][q] = fma2(ap, bp[q], acc[r][q]);
            }
        }
    }

    float* ob = g_att + ((size_t)b * NPIX + i0 + ty * 8) * NPIX + j0 + tx * 8;
#pragma unroll
    for (int r = 0; r < 8; r++) {
        float v[8];
#pragma unroll
        for (int q = 0; q < 4; q++) unpack2(acc[r][q], v[2 * q], v[2 * q + 1]);
#pragma unroll
        for (int m = 0; m < 8; m++)
            v[m] = __fdividef(1.f, 1.f + __expf(-v[m]));
        *(float4*)(ob + (size_t)r * NPIX)     = make_float4(v[0], v[1], v[2], v[3]);
        *(float4*)(ob + (size_t)r * NPIX + 4) = make_float4(v[4], v[5], v[6], v[7]);
    }
}

// ---------------------------------------------------------------------------
// Kernel 5: self_v GEMM + p_v add.  o_v[c,i] = V[c,i]*p[i] + sum_j V[c,j]att[i,j]
// Block tile: 128(c) x 128(i), contraction j in chunks of 16 (transpose loads).
// grid (32 it, 4), block 256.
// ---------------------------------------------------------------------------
__global__ __launch_bounds__(256, 2) void k_attv(const float* __restrict__ p)
{
    __shared__ __align__(16) float As[16][136];   // [j][c]
    __shared__ __align__(16) float Bs[16][136];   // [j][i]

    const int b  = blockIdx.y;
    const int i0 = blockIdx.x * 128;
    const int tid = threadIdx.x;
    const int tx = tid & 15, ty = tid >> 4;

    const float* Vb = g_v + (size_t)b * CATT * NPIX;
    const float* Ab = g_att + (size_t)b * NPIX * NPIX;

    const int lr = tid >> 1;          // 0..127 (c for A, i for B)
    const int ls = (tid & 1) * 8;     // 0 or 8  (j offset)

    unsigned long long acc[8][4];
#pragma unroll
    for (int r = 0; r < 8; r++)
#pragma unroll
        for (int q = 0; q < 4; q++) acc[r][q] = 0ull;

    for (int j0 = 0; j0 < NPIX; j0 += 16) {
        const float* ga = Vb + (size_t)lr * NPIX + j0 + ls;
        const float* gb = Ab + (size_t)(i0 + lr) * NPIX + j0 + ls;
        float4 a0 = *(const float4*)ga;
        float4 a1 = *(const float4*)(ga + 4);
        float4 b0 = *(const float4*)gb;
        float4 b1 = *(const float4*)(gb + 4);
        __syncthreads();
        As[ls + 0][lr] = a0.x; As[ls + 1][lr] = a0.y;
        As[ls + 2][lr] = a0.z; As[ls + 3][lr] = a0.w;
        As[ls + 4][lr] = a1.x; As[ls + 5][lr] = a1.y;
        As[ls + 6][lr] = a1.z; As[ls + 7][lr] = a1.w;
        Bs[ls + 0][lr] = b0.x; Bs[ls + 1][lr] = b0.y;
        Bs[ls + 2][lr] = b0.z; Bs[ls + 3][lr] = b0.w;
        Bs[ls + 4][lr] = b1.x; Bs[ls + 5][lr] = b1.y;
        Bs[ls + 6][lr] = b1.z; Bs[ls + 7][lr] = b1.w;
        __syncthreads();
#pragma unroll
        for (int kk = 0; kk < 16; kk++) {
            float4 av0 = *(const float4*)&As[kk][ty * 8];
            float4 av1 = *(const float4*)&As[kk][ty * 8 + 4];
            ulonglong2 bv0 = *(const ulonglong2*)&Bs[kk][tx * 8];
            ulonglong2 bv1 = *(const ulonglong2*)&Bs[kk][tx * 8 + 4];
            unsigned long long bp[4] = { bv0.x, bv0.y, bv1.x, bv1.y };
            float av[8] = { av0.x, av0.y, av0.z, av0.w,
                            av1.x, av1.y, av1.z, av1.w };
#pragma unroll
            for (int r = 0; r < 8; r++) {
                unsigned long long ap = pack2(av[r], av[r]);
#pragma unroll
                for (int q = 0; q < 4; q++)
                    acc[r][q] = fma2(ap, bp[q], acc[r][q]);
            }
        }
    }

    // epilogue: += V*p, write o_v
    const float* pb = p + (size_t)b * NPIX + i0 + tx * 8;
    const float* vb = Vb + (size_t)(ty * 8) * NPIX + i0 + tx * 8;
    float* ob = g_ov + ((size_t)b * CATT + ty * 8) * NPIX + i0 + tx * 8;
#pragma unroll
    for (int r = 0; r < 8; r++) {
        float v[8];
#pragma unroll
        for (int q = 0; q < 4; q++) unpack2(acc[r][q], v[2 * q], v[2 * q + 1]);
#pragma unroll
        for (int m = 0; m < 8; m++)
            v[m] = fmaf(vb[(size_t)r * NPIX + m], pb[m], v[m]);
        *(float4*)(ob + (size_t)r * NPIX)     = make_float4(v[0], v[1], v[2], v[3]);
        *(float4*)(ob + (size_t)r * NPIX + 4) = make_float4(v[4], v[5], v[6], v[7]);
    }
}

// ---------------------------------------------------------------------------
// Kernel 6: bottleneck 1x1 (64x128) + BN + PReLU -> out (4,64,64,64)
// grid (64,4), block 256. o_v tile (128x64) staged in smem; bt_w via uniform ldg.
// ---------------------------------------------------------------------------
__global__ __launch_bounds__(256) void k_bt(
    const float* __restrict__ bt_w, const float* __restrict__ bt_b,
    const float* __restrict__ bn2_g, const float* __restrict__ bn2_b,
    const float* __restrict__ bn2_m, const float* __restrict__ bn2_v,
    const float* __restrict__ prelu2, float* __restrict__ out)
{
    __shared__ float ovs[128][64];
    const int b  = blockIdx.y;
    const int i0 = blockIdx.x * 64;
    const int tid = threadIdx.x;

    for (int idx = tid; idx < 128 * 64; idx += 256) {
        int c = idx >> 6, ii = idx & 63;
        ovs[c][ii] = g_ov[((size_t)b * CATT + c) * NPIX + i0 + ii];
    }
    __syncthreads();

    const int il = tid & 63, og = tid >> 6;   // og 0..3 -> 16 outputs each
    float accs[16];
#pragma unroll
    for (int n = 0; n < 16; n++) accs[n] = 0.f;

    for (int c = 0; c < 128; c++) {
        float v = ovs[c][il];
#pragma unroll
        for (int n = 0; n < 16; n++)
            accs[n] = fmaf(__ldg(bt_w + (og * 16 + n) * 128 + c), v, accs[n]);
    }

    const float a = prelu2[0];
#pragma unroll
    for (int n = 0; n < 16; n++) {
        int o = og * 16 + n;
        float y  = accs[n] + bt_b[o];
        float sc = bn2_g[o] * rsqrtf(bn2_v[o] + EPS);
        y = (y - bn2_m[o]) * sc + bn2_b[o];
        y = (y >= 0.f) ? y : a * y;
        out[((size_t)b * 64 + o) * NPIX + i0 + il] = y;
    }
}

// ---------------------------------------------------------------------------
extern "C" void kernel_launch(void* const* d_in, const int* in_sizes, int n_in,
                              void* d_out, int out_size)
{
    const float* em     = (const float*)d_in[0];
    const float* dm     = (const float*)d_in[1];
    const float* p      = (const float*)d_in[2];
    const float* en_w   = (const float*)d_in[3];
    const float* en_b   = (const float*)d_in[4];
    const float* bn1_g  = (const float*)d_in[5];
    const float* bn1_b  = (const float*)d_in[6];
    const float* bn1_m  = (const float*)d_in[7];
    const float* bn1_v  = (const float*)d_in[8];
    const float* prelu1 = (const float*)d_in[9];
    const float* dw_w   = (const float*)d_in[10];
    const float* dw_b   = (const float*)d_in[11];
    const float* de_w   = (const float*)d_in[12];
    const float* de_b   = (const float*)d_in[13];
    const float* q_w    = (const float*)d_in[14];
    const float* q_b    = (const float*)d_in[15];
    const float* k_w    = (const float*)d_in[16];
    const float* k_b    = (const float*)d_in[17];
    const float* v_w    = (const float*)d_in[18];
    const float* v_b    = (const float*)d_in[19];
    const float* bt_w   = (const float*)d_in[20];
    const float* bt_b   = (const float*)d_in[21];
    const float* bn2_g  = (const float*)d_in[22];
    const float* bn2_b  = (const float*)d_in[23];
    const float* bn2_m  = (const float*)d_in[24];
    const float* bn2_v  = (const float*)d_in[25];
    const float* prelu2 = (const float*)d_in[26];

    k_conv3  <<<dim3(8, 8, 4),   dim3(16, 16)>>>(em, en_w, en_b, bn1_g, bn1_b,
                                                 bn1_m, bn1_v, prelu1);
    k_build_f<<<dim3(16, 48, 4), 256>>>(dm, de_w, de_b, dw_w, dw_b);
    k_qkv    <<<dim3(16, 4),     256>>>(q_w, q_b, k_w, k_b, v_w, v_b);
    k_energy <<<dim3(32, 32, 4), 256>>>();
    k_attv   <<<dim3(32, 4),     256>>>(p);
    k_bt     <<<dim3(64, 4),     256>>>(bt_w, bt_b, bn2_g, bn2_b, bn2_m, bn2_v,
                                        prelu2, (float*)d_out);
}

// round 3
// speedup vs baseline: 2.1997x; 2.1997x over previous
#include <cuda_runtime.h>
#include <cuda_bf16.h>
#include <cstdint>

#define BATCH 4
#define NPIX  4096
#define CATT  128
#define EPS   1e-5f

// ---------------- device scratch ------------------------------------------
__device__ float g_tmp[BATCH * 16 * 128 * 128];                 // conv out
__device__ float g_f  [BATCH * 48 * NPIX];                      // fused feats
__device__ __nv_bfloat16 g_qhi[(size_t)BATCH * NPIX * CATT];    // [b][i][c]
__device__ __nv_bfloat16 g_qlo[(size_t)BATCH * NPIX * CATT];
__device__ __nv_bfloat16 g_khi[(size_t)BATCH * NPIX * CATT];    // [b][j][c]
__device__ __nv_bfloat16 g_klo[(size_t)BATCH * NPIX * CATT];
__device__ __nv_bfloat16 g_vhi[(size_t)BATCH * CATT * NPIX];    // [b][c][j]
__device__ __nv_bfloat16 g_vlo[(size_t)BATCH * CATT * NPIX];
__device__ float g_att[(size_t)BATCH * NPIX * NPIX];            // 268 MB f32
__device__ float g_ov [BATCH * CATT * NPIX];                    // V*p + self_v

// ---------------- helpers --------------------------------------------------
__device__ __forceinline__ uint32_t smem_u32(const void* smem_ptr) {
    uint32_t addr;
    asm("{ .reg .u64 tmp; cvta.to.shared.u64 tmp, %1; cvt.u32.u64 %0, tmp; }"
        : "=r"(addr) : "l"(smem_ptr));
    return addr;
}

__device__ __forceinline__ void ldmx4(uint32_t* r, uint32_t addr) {
    asm volatile("ldmatrix.sync.aligned.m8n8.x4.shared.b16 {%0,%1,%2,%3}, [%4];"
        : "=r"(r[0]), "=r"(r[1]), "=r"(r[2]), "=r"(r[3]) : "r"(addr));
}

__device__ __forceinline__ void mma16816(float* c, const uint32_t* a,
                                         const uint32_t* b) {
    asm volatile(
        "mma.sync.aligned.m16n8k16.row.col.f32.bf16.bf16.f32 "
        "{%0,%1,%2,%3}, {%4,%5,%6,%7}, {%8,%9}, {%0,%1,%2,%3};"
        : "+f"(c[0]), "+f"(c[1]), "+f"(c[2]), "+f"(c[3])
        : "r"(a[0]), "r"(a[1]), "r"(a[2]), "r"(a[3]), "r"(b[0]), "r"(b[1]));
}

#define SPAD 40   // bf16 row stride (32 data + 8 pad) = 80B, ldmatrix conflict-free

// ---------------------------------------------------------------------------
// Kernel 1: conv3x3(em) + BN + PReLU  -> g_tmp
// ---------------------------------------------------------------------------
__global__ __launch_bounds__(256) void k_conv3(
    const float* __restrict__ em, const float* __restrict__ en_w,
    const float* __restrict__ en_b, const float* __restrict__ bn1_g,
    const float* __restrict__ bn1_b, const float* __restrict__ bn1_m,
    const float* __restrict__ bn1_v, const float* __restrict__ prelu1)
{
    __shared__ float ws[16 * 64 * 9];
    __shared__ float tile[18 * 18];
    const int tid = threadIdx.y * 16 + threadIdx.x;
    for (int idx = tid; idx < 16 * 64 * 9; idx += 256) ws[idx] = en_w[idx];

    const int b  = blockIdx.z;
    const int gx = blockIdx.x * 16 + threadIdx.x;
    const int gy = blockIdx.y * 16 + threadIdx.y;

    float acc[16];
#pragma unroll
    for (int o = 0; o < 16; o++) acc[o] = 0.f;
    const float* emb = em + (size_t)b * 64 * 128 * 128;

    for (int ci = 0; ci < 64; ci++) {
        __syncthreads();
        for (int idx = tid; idx < 18 * 18; idx += 256) {
            int r = idx / 18, c = idx % 18;
            int yy = (int)blockIdx.y * 16 + r - 1;
            int xx = (int)blockIdx.x * 16 + c - 1;
            float v = 0.f;
            if (yy >= 0 && yy < 128 && xx >= 0 && xx < 128)
                v = emb[(size_t)ci * 16384 + yy * 128 + xx];
            tile[idx] = v;
        }
        __syncthreads();
        float t[9];
#pragma unroll
        for (int kh = 0; kh < 3; kh++)
#pragma unroll
            for (int kw = 0; kw < 3; kw++)
                t[kh * 3 + kw] = tile[(threadIdx.y + kh) * 18 + threadIdx.x + kw];
        const float* w = ws + ci * 9;
#pragma unroll
        for (int o = 0; o < 16; o++)
#pragma unroll
            for (int k = 0; k < 9; k++)
                acc[o] = fmaf(w[o * 576 + k], t[k], acc[o]);
    }

    const float a = prelu1[0];
#pragma unroll
    for (int o = 0; o < 16; o++) {
        float y  = acc[o] + en_b[o];
        float sc = bn1_g[o] * rsqrtf(bn1_v[o] + EPS);
        y = (y - bn1_m[o]) * sc + bn1_b[o];
        y = (y >= 0.f) ? y : a * y;
        g_tmp[(((size_t)b * 16 + o) * 128 + gy) * 128 + gx] = y;
    }
}

// ---------------------------------------------------------------------------
// Kernel 2: build f
// ---------------------------------------------------------------------------
__global__ __launch_bounds__(256) void k_build_f(
    const float* __restrict__ dm, const float* __restrict__ de_w,
    const float* __restrict__ de_b, const float* __restrict__ dw_w,
    const float* __restrict__ dw_b)
{
    const int b  = blockIdx.z;
    const int ch = blockIdx.y;
    const int i  = blockIdx.x * 256 + threadIdx.x;
    float out;
    if (ch < 16) {
        const int ph = i >> 6, pw = i & 63;
        float m = -1e30f;
        const float* tb = g_tmp + ((size_t)b * 16 + ch) * 16384;
#pragma unroll
        for (int dy = 0; dy < 3; dy++) {
            int y = 2 * ph - 1 + dy;
            if (y < 0 || y > 127) continue;
#pragma unroll
            for (int dx = 0; dx < 3; dx++) {
                int x = 2 * pw - 1 + dx;
                if (x < 0 || x > 127) continue;
                m = fmaxf(m, tb[y * 128 + x]);
            }
        }
        out = m * dw_w[ch] + dw_b[ch];
    } else {
        const int co = ch - 16;
        float accv = de_b[co];
        const float* dmb = dm + (size_t)b * 128 * NPIX + i;
        const float* w   = de_w + co * 128;
#pragma unroll 8
        for (int c = 0; c < 128; c++)
            accv = fmaf(__ldg(w + c), __ldg(dmb + (size_t)c * NPIX), accv);
        out = accv;
    }
    g_f[((size_t)b * 48 + ch) * NPIX + i] = out;
}

// ---------------------------------------------------------------------------
// Kernel 3: QKV -> split-bf16 planes (+ g_ov = V*p)
// grid (16, 3, 4), 256 thr
// ---------------------------------------------------------------------------
__global__ __launch_bounds__(256) void k_qkv_t(
    const float* __restrict__ q_w, const float* __restrict__ q_b,
    const float* __restrict__ k_w, const float* __restrict__ k_b,
    const float* __restrict__ v_w, const float* __restrict__ v_b,
    const float* __restrict__ p)
{
    const int b    = blockIdx.z;
    const int proj = blockIdx.y;
    const int i    = blockIdx.x * 256 + threadIdx.x;

    float fv[48];
#pragma unroll
    for (int k = 0; k < 48; k++)
        fv[k] = g_f[((size_t)b * 48 + k) * NPIX + i];

    const float* w  = (proj == 0) ? q_w : (proj == 1) ? k_w : v_w;
    const float* bb = (proj == 0) ? q_b : (proj == 1) ? k_b : v_b;

    if (proj < 2) {
        __nv_bfloat16* hi = ((proj == 0) ? g_qhi : g_khi) + ((size_t)b * NPIX + i) * CATT;
        __nv_bfloat16* lo = ((proj == 0) ? g_qlo : g_klo) + ((size_t)b * NPIX + i) * CATT;
        for (int c8 = 0; c8 < 16; c8++) {
            uint4 hib, lob;
            __nv_bfloat16* hb = (__nv_bfloat16*)&hib;
            __nv_bfloat16* lb = (__nv_bfloat16*)&lob;
#pragma unroll
            for (int cc = 0; cc < 8; cc++) {
                int c = c8 * 8 + cc;
                float accv = __ldg(bb + c);
                const float* wr = w + c * 48;
#pragma unroll
                for (int k = 0; k < 48; k++)
                    accv = fmaf(__ldg(wr + k), fv[k], accv);
                __nv_bfloat16 h = __float2bfloat16(accv);
                hb[cc] = h;
                lb[cc] = __float2bfloat16(accv - __bfloat162float(h));
            }
            *(uint4*)(hi + c8 * 8) = hib;
            *(uint4*)(lo + c8 * 8) = lob;
        }
    } else {
        const float pv = p[(size_t)b * NPIX + i];
        for (int c = 0; c < 128; c++) {
            float accv = __ldg(bb + c);
            const float* wr = w + c * 48;
#pragma unroll
            for (int k = 0; k < 48; k++)
                accv = fmaf(__ldg(wr + k), fv[k], accv);
            __nv_bfloat16 h = __float2bfloat16(accv);
            size_t off = ((size_t)b * CATT + c) * NPIX + i;
            g_vhi[off] = h;
            g_vlo[off] = __float2bfloat16(accv - __bfloat162float(h));
            g_ov[off]  = accv * pv;
        }
    }
}

// ---------------------------------------------------------------------------
// Kernel 4: GEMM1 (HMMA): att[i][j] = sigmoid(sum_c Q[i][c] K[j][c])
// 128x128 tile; 8 warps 2x4 (64x32 each); 3-pass hi/lo bf16 split.
// grid (32 jt, 32 it, 4), 256 thr.
// ---------------------------------------------------------------------------
__global__ __launch_bounds__(256, 2) void k_gemm1()
{
    __shared__ __align__(16) __nv_bfloat16 sAh[128 * SPAD], sAl[128 * SPAD];
    __shared__ __align__(16) __nv_bfloat16 sBh[128 * SPAD], sBl[128 * SPAD];

    const int tid  = threadIdx.x;
    const int lane = tid & 31;
    const int warp = tid >> 5;
    const int wm = (warp & 1) * 64;     // 2 warps in m
    const int wn = (warp >> 1) * 32;    // 4 warps in n
    const int b  = blockIdx.z;
    const int i0 = blockIdx.y * 128;
    const int j0 = blockIdx.x * 128;

    const __nv_bfloat16* Ah = g_qhi + ((size_t)b * NPIX + i0) * CATT;
    const __nv_bfloat16* Al = g_qlo + ((size_t)b * NPIX + i0) * CATT;
    const __nv_bfloat16* Bh = g_khi + ((size_t)b * NPIX + j0) * CATT;
    const __nv_bfloat16* Bl = g_klo + ((size_t)b * NPIX + j0) * CATT;

    float acc[4][4][4];
#pragma unroll
    for (int mi = 0; mi < 4; mi++)
#pragma unroll
        for (int ni = 0; ni < 4; ni++)
#pragma unroll
            for (int q = 0; q < 4; q++) acc[mi][ni][q] = 0.f;

    const uint32_t uAh = smem_u32(sAh), uAl = smem_u32(sAl);
    const uint32_t uBh = smem_u32(sBh), uBl = smem_u32(sBl);

    for (int c0 = 0; c0 < 128; c0 += 32) {
        __syncthreads();
#pragma unroll
        for (int t = 0; t < 2; t++) {
            int idx = tid + t * 256;          // 0..511
            int r = idx >> 2, s = (idx & 3) * 8;
            size_t go = (size_t)r * CATT + c0 + s;
            int so = r * SPAD + s;
            *(uint4*)&sAh[so] = *(const uint4*)(Ah + go);
            *(uint4*)&sAl[so] = *(const uint4*)(Al + go);
            *(uint4*)&sBh[so] = *(const uint4*)(Bh + go);
            *(uint4*)&sBl[so] = *(const uint4*)(Bl + go);
        }
        __syncthreads();
#pragma unroll
        for (int ks = 0; ks < 2; ks++) {
            const int k0 = ks * 16;
            const uint32_t aoff =
                (uint32_t)(((wm + (lane & 15)) * SPAD + k0 + ((lane >> 4) << 3)) * 2);
            const uint32_t boff =
                (uint32_t)(((wn + (lane & 7) + ((lane >> 4) << 3)) * SPAD +
                            k0 + (((lane >> 3) & 1) << 3)) * 2);
            uint32_t ah[4][4], al[4][4];
#pragma unroll
            for (int mi = 0; mi < 4; mi++) {
                ldmx4(ah[mi], uAh + aoff + mi * 16 * SPAD * 2);
                ldmx4(al[mi], uAl + aoff + mi * 16 * SPAD * 2);
            }
#pragma unroll
            for (int nj = 0; nj < 2; nj++) {
                uint32_t bh[4], bl[4];
                ldmx4(bh, uBh + boff + nj * 16 * SPAD * 2);
                ldmx4(bl, uBl + boff + nj * 16 * SPAD * 2);
#pragma unroll
                for (int mi = 0; mi < 4; mi++) {
                    mma16816(acc[mi][2 * nj],     ah[mi], bh);
                    mma16816(acc[mi][2 * nj],     al[mi], bh);
                    mma16816(acc[mi][2 * nj],     ah[mi], bl);
                    mma16816(acc[mi][2 * nj + 1], ah[mi], bh + 2);
                    mma16816(acc[mi][2 * nj + 1], al[mi], bh + 2);
                    mma16816(acc[mi][2 * nj + 1], ah[mi], bl + 2);
                }
            }
        }
    }

    // epilogue: sigmoid + f32 store
    float* ob = g_att + ((size_t)b * NPIX + i0) * NPIX + j0;
#pragma unroll
    for (int mi = 0; mi < 4; mi++) {
        int r0 = wm + mi * 16 + (lane >> 2);
#pragma unroll
        for (int ni = 0; ni < 4; ni++) {
            int cc = wn + ni * 8 + 2 * (lane & 3);
            float s0 = __fdividef(1.f, 1.f + __expf(-acc[mi][ni][0]));
            float s1 = __fdividef(1.f, 1.f + __expf(-acc[mi][ni][1]));
            float s2 = __fdividef(1.f, 1.f + __expf(-acc[mi][ni][2]));
            float s3 = __fdividef(1.f, 1.f + __expf(-acc[mi][ni][3]));
            *(float2*)(ob + (size_t)r0 * NPIX + cc)       = make_float2(s0, s1);
            *(float2*)(ob + (size_t)(r0 + 8) * NPIX + cc) = make_float2(s2, s3);
        }
    }
}

// ---------------------------------------------------------------------------
// Kernel 5: GEMM2 (HMMA, split-K over j): g_ov[c][i] += sum_j V[c][j] att[i][j]
// grid (8 jc, 32 it, 4), 256 thr.
// ---------------------------------------------------------------------------
__global__ __launch_bounds__(256, 2) void k_gemm2()
{
    __shared__ __align__(16) __nv_bfloat16 sAh[128 * SPAD], sAl[128 * SPAD];
    __shared__ __align__(16) __nv_bfloat16 sBh[128 * SPAD], sBl[128 * SPAD];

    const int tid  = threadIdx.x;
    const int lane = tid & 31;
    const int warp = tid >> 5;
    const int wm = (warp & 1) * 64;     // m = c
    const int wn = (warp >> 1) * 32;    // n = i
    const int b   = blockIdx.z;
    const int i0  = blockIdx.y * 128;
    const int jc0 = blockIdx.x * 512;

    const __nv_bfloat16* Vh = g_vhi + (size_t)b * CATT * NPIX;
    const __nv_bfloat16* Vl = g_vlo + (size_t)b * CATT * NPIX;
    const float* attb = g_att + ((size_t)b * NPIX + i0) * NPIX;

    float acc[4][4][4];
#pragma unroll
    for (int mi = 0; mi < 4; mi++)
#pragma unroll
        for (int ni = 0; ni < 4; ni++)
#pragma unroll
            for (int q = 0; q < 4; q++) acc[mi][ni][q] = 0.f;

    const uint32_t uAh = smem_u32(sAh), uAl = smem_u32(sAl);
    const uint32_t uBh = smem_u32(sBh), uBl = smem_u32(sBl);

    for (int st = 0; st < 16; st++) {
        const int j0 = jc0 + st * 32;
        __syncthreads();
        // A: V hi/lo planes (natural [c][j])
#pragma unroll
        for (int t = 0; t < 2; t++) {
            int idx = tid + t * 256;
            int r = idx >> 2, s = (idx & 3) * 8;
            size_t go = (size_t)r * NPIX + j0 + s;
            int so = r * SPAD + s;
            *(uint4*)&sAh[so] = *(const uint4*)(Vh + go);
            *(uint4*)&sAl[so] = *(const uint4*)(Vl + go);
        }
        // B: att f32 -> hi/lo bf16 split on the fly ([i][j])
#pragma unroll
        for (int t = 0; t < 4; t++) {
            int idx = tid + t * 256;          // 0..1023
            int r = idx >> 3, s = (idx & 7) * 4;
            float4 v = *(const float4*)(attb + (size_t)r * NPIX + j0 + s);
            __nv_bfloat16 h0 = __float2bfloat16(v.x);
            __nv_bfloat16 h1 = __float2bfloat16(v.y);
            __nv_bfloat16 h2 = __float2bfloat16(v.z);
            __nv_bfloat16 h3 = __float2bfloat16(v.w);
            uint2 hp, lp;
            __nv_bfloat16* hh = (__nv_bfloat16*)&hp;
            __nv_bfloat16* ll = (__nv_bfloat16*)&lp;
            hh[0] = h0; hh[1] = h1; hh[2] = h2; hh[3] = h3;
            ll[0] = __float2bfloat16(v.x - __bfloat162float(h0));
            ll[1] = __float2bfloat16(v.y - __bfloat162float(h1));
            ll[2] = __float2bfloat16(v.z - __bfloat162float(h2));
            ll[3] = __float2bfloat16(v.w - __bfloat162float(h3));
            int so = r * SPAD + s;
            *(uint2*)&sBh[so] = hp;
            *(uint2*)&sBl[so] = lp;
        }
        __syncthreads();
#pragma unroll
        for (int ks = 0; ks < 2; ks++) {
            const int k0 = ks * 16;
            const uint32_t aoff =
                (uint32_t)(((wm + (lane & 15)) * SPAD + k0 + ((lane >> 4) << 3)) * 2);
            const uint32_t boff =
                (uint32_t)(((wn + (lane & 7) + ((lane >> 4) << 3)) * SPAD +
                            k0 + (((lane >> 3) & 1) << 3)) * 2);
            uint32_t ah[4][4], al[4][4];
#pragma unroll
            for (int mi = 0; mi < 4; mi++) {
                ldmx4(ah[mi], uAh + aoff + mi * 16 * SPAD * 2);
                ldmx4(al[mi], uAl + aoff + mi * 16 * SPAD * 2);
            }
#pragma unroll
            for (int nj = 0; nj < 2; nj++) {
                uint32_t bh[4], bl[4];
                ldmx4(bh, uBh + boff + nj * 16 * SPAD * 2);
                ldmx4(bl, uBl + boff + nj * 16 * SPAD * 2);
#pragma unroll
                for (int mi = 0; mi < 4; mi++) {
                    mma16816(acc[mi][2 * nj],     ah[mi], bh);
                    mma16816(acc[mi][2 * nj],     al[mi], bh);
                    mma16816(acc[mi][2 * nj],     ah[mi], bl);
                    mma16816(acc[mi][2 * nj + 1], ah[mi], bh + 2);
                    mma16816(acc[mi][2 * nj + 1], al[mi], bh + 2);
                    mma16816(acc[mi][2 * nj + 1], ah[mi], bl + 2);
                }
            }
        }
    }

    // epilogue: atomicAdd into g_ov (c rows, i cols)
    float* ob = g_ov + ((size_t)b * CATT) * NPIX + i0;
#pragma unroll
    for (int mi = 0; mi < 4; mi++) {
        int c0 = wm + mi * 16 + (lane >> 2);
#pragma unroll
        for (int ni = 0; ni < 4; ni++) {
            int ii = wn + ni * 8 + 2 * (lane & 3);
            atomicAdd(ob + (size_t)c0 * NPIX + ii,           acc[mi][ni][0]);
            atomicAdd(ob + (size_t)c0 * NPIX + ii + 1,       acc[mi][ni][1]);
            atomicAdd(ob + (size_t)(c0 + 8) * NPIX + ii,     acc[mi][ni][2]);
            atomicAdd(ob + (size_t)(c0 + 8) * NPIX + ii + 1, acc[mi][ni][3]);
        }
    }
}

// ---------------------------------------------------------------------------
// Kernel 6: bottleneck 1x1 + BN + PReLU -> out
// ---------------------------------------------------------------------------
__global__ __launch_bounds__(256) void k_bt(
    const float* __restrict__ bt_w, const float* __restrict__ bt_b,
    const float* __restrict__ bn2_g, const float* __restrict__ bn2_b,
    const float* __restrict__ bn2_m, const float* __restrict__ bn2_v,
    const float* __restrict__ prelu2, float* __restrict__ out)
{
    __shared__ float ovs[128][64];
    const int b  = blockIdx.y;
    const int i0 = blockIdx.x * 64;
    const int tid = threadIdx.x;

    for (int idx = tid; idx < 128 * 64; idx += 256) {
        int c = idx >> 6, ii = idx & 63;
        ovs[c][ii] = g_ov[((size_t)b * CATT + c) * NPIX + i0 + ii];
    }
    __syncthreads();

    const int il = tid & 63, og = tid >> 6;
    float accs[16];
#pragma unroll
    for (int n = 0; n < 16; n++) accs[n] = 0.f;

    for (int c = 0; c < 128; c++) {
        float v = ovs[c][il];
#pragma unroll
        for (int n = 0; n < 16; n++)
            accs[n] = fmaf(__ldg(bt_w + (og * 16 + n) * 128 + c), v, accs[n]);
    }

    const float a = prelu2[0];
#pragma unroll
    for (int n = 0; n < 16; n++) {
        int o = og * 16 + n;
        float y  = accs[n] + bt_b[o];
        float sc = bn2_g[o] * rsqrtf(bn2_v[o] + EPS);
        y = (y - bn2_m[o]) * sc + bn2_b[o];
        y = (y >= 0.f) ? y : a * y;
        out[((size_t)b * 64 + o) * NPIX + i0 + il] = y;
    }
}

// ---------------------------------------------------------------------------
extern "C" void kernel_launch(void* const* d_in, const int* in_sizes, int n_in,
                              void* d_out, int out_size)
{
    const float* em     = (const float*)d_in[0];
    const float* dm     = (const float*)d_in[1];
    const float* p      = (const float*)d_in[2];
    const float* en_w   = (const float*)d_in[3];
    const float* en_b   = (const float*)d_in[4];
    const float* bn1_g  = (const float*)d_in[5];
    const float* bn1_b  = (const float*)d_in[6];
    const float* bn1_m  = (const float*)d_in[7];
    const float* bn1_v  = (const float*)d_in[8];
    const float* prelu1 = (const float*)d_in[9];
    const float* dw_w   = (const float*)d_in[10];
    const float* dw_b   = (const float*)d_in[11];
    const float* de_w   = (const float*)d_in[12];
    const float* de_b   = (const float*)d_in[13];
    const float* q_w    = (const float*)d_in[14];
    const float* q_b    = (const float*)d_in[15];
    const float* k_w    = (const float*)d_in[16];
    const float* k_b    = (const float*)d_in[17];
    const float* v_w    = (const float*)d_in[18];
    const float* v_b    = (const float*)d_in[19];
    const float* bt_w   = (const float*)d_in[20];
    const float* bt_b   = (const float*)d_in[21];
    const float* bn2_g  = (const float*)d_in[22];
    const float* bn2_b  = (const float*)d_in[23];
    const float* bn2_m  = (const float*)d_in[24];
    const float* bn2_v  = (const float*)d_in[25];
    const float* prelu2 = (const float*)d_in[26];

    k_conv3  <<<dim3(8, 8, 4),   dim3(16, 16)>>>(em, en_w, en_b, bn1_g, bn1_b,
                                                 bn1_m, bn1_v, prelu1);
    k_build_f<<<dim3(16, 48, 4), 256>>>(dm, de_w, de_b, dw_w, dw_b);
    k_qkv_t  <<<dim3(16, 3, 4),  256>>>(q_w, q_b, k_w, k_b, v_w, v_b, p);
    k_gemm1  <<<dim3(32, 32, 4), 256>>>();
    k_gemm2  <<<dim3(8, 32, 4),  256>>>();
    k_bt     <<<dim3(64, 4),     256>>>(bt_w, bt_b, bn2_g, bn2_b, bn2_m, bn2_v,
                                        prelu2, (float*)d_out);
}

// round 4
// speedup vs baseline: 2.9307x; 1.3323x over previous
#include <cuda_runtime.h>
#include <cuda_bf16.h>
#include <cstdint>

#define BATCH 4
#define NPIX  4096
#define CATT  128
#define EPS   1e-5f

// ---------------- device scratch ------------------------------------------
__device__ float g_tmp[BATCH * 16 * 128 * 128];
__device__ float g_f  [BATCH * 48 * NPIX];
__device__ __nv_bfloat16 g_qhi[(size_t)BATCH * NPIX * CATT];    // [b][i][c]
__device__ __nv_bfloat16 g_qlo[(size_t)BATCH * NPIX * CATT];
__device__ __nv_bfloat16 g_khi[(size_t)BATCH * NPIX * CATT];    // [b][j][c]
__device__ __nv_bfloat16 g_klo[(size_t)BATCH * NPIX * CATT];
__device__ __nv_bfloat16 g_vhi[(size_t)BATCH * CATT * NPIX];    // [b][c][j]
__device__ __nv_bfloat16 g_vlo[(size_t)BATCH * CATT * NPIX];
__device__ __nv_bfloat16 g_atth[(size_t)BATCH * NPIX * NPIX];   // att hi plane
__device__ __nv_bfloat16 g_attl[(size_t)BATCH * NPIX * NPIX];   // att lo plane
__device__ float g_ov [BATCH * CATT * NPIX];

// ---------------- helpers --------------------------------------------------
__device__ __forceinline__ uint32_t smem_u32(const void* smem_ptr) {
    uint32_t addr;
    asm("{ .reg .u64 tmp; cvta.to.shared.u64 tmp, %1; cvt.u32.u64 %0, tmp; }"
        : "=r"(addr) : "l"(smem_ptr));
    return addr;
}
__device__ __forceinline__ void ldmx4(uint32_t* r, uint32_t addr) {
    asm volatile("ldmatrix.sync.aligned.m8n8.x4.shared.b16 {%0,%1,%2,%3}, [%4];"
        : "=r"(r[0]), "=r"(r[1]), "=r"(r[2]), "=r"(r[3]) : "r"(addr));
}
__device__ __forceinline__ void mma16816(float* c, const uint32_t* a,
                                         const uint32_t* b) {
    asm volatile(
        "mma.sync.aligned.m16n8k16.row.col.f32.bf16.bf16.f32 "
        "{%0,%1,%2,%3}, {%4,%5,%6,%7}, {%8,%9}, {%0,%1,%2,%3};"
        : "+f"(c[0]), "+f"(c[1]), "+f"(c[2]), "+f"(c[3])
        : "r"(a[0]), "r"(a[1]), "r"(a[2]), "r"(a[3]), "r"(b[0]), "r"(b[1]));
}
__device__ __forceinline__ void cp16(uint32_t dst, const void* src) {
    asm volatile("cp.async.ca.shared.global [%0], [%1], 16;"
                 :: "r"(dst), "l"(src) : "memory");
}
#define CP_COMMIT() asm volatile("cp.async.commit_group;" ::: "memory")
#define CP_WAIT1()  asm volatile("cp.async.wait_group 1;" ::: "memory")
#define CP_WAIT0()  asm volatile("cp.async.wait_group 0;" ::: "memory")

#define SPAD 40                       // bf16 row stride; 80B rows, ldmatrix-safe
#define PLANE_B (128 * SPAD * 2)      // 10240 bytes per plane
#define G_SMEM  (8 * PLANE_B)         // 2 buffers x 4 planes = 80 KB

// pack two bf16 into u32
__device__ __forceinline__ uint32_t pk2bf(float a, float b) {
    __nv_bfloat16 ha = __float2bfloat16(a), hb = __float2bfloat16(b);
    return (uint32_t)__bfloat16_as_ushort(ha) |
           ((uint32_t)__bfloat16_as_ushort(hb) << 16);
}

// ---------------------------------------------------------------------------
// Kernel 1: conv3x3(em) + BN + PReLU  -> g_tmp  (4 channels per sync round)
// ---------------------------------------------------------------------------
__global__ __launch_bounds__(256) void k_conv3(
    const float* __restrict__ em, const float* __restrict__ en_w,
    const float* __restrict__ en_b, const float* __restrict__ bn1_g,
    const float* __restrict__ bn1_b, const float* __restrict__ bn1_m,
    const float* __restrict__ bn1_v, const float* __restrict__ prelu1)
{
    __shared__ float ws[16 * 64 * 9];
    __shared__ float tile[4][18 * 18];
    const int tid = threadIdx.y * 16 + threadIdx.x;
    for (int idx = tid; idx < 16 * 64 * 9; idx += 256) ws[idx] = en_w[idx];

    const int b  = blockIdx.z;
    const int gx = blockIdx.x * 16 + threadIdx.x;
    const int gy = blockIdx.y * 16 + threadIdx.y;

    float acc[16];
#pragma unroll
    for (int o = 0; o < 16; o++) acc[o] = 0.f;
    const float* emb = em + (size_t)b * 64 * 128 * 128;

    for (int ci0 = 0; ci0 < 64; ci0 += 4) {
        __syncthreads();
        for (int idx = tid; idx < 4 * 324; idx += 256) {
            int c = idx / 324, rem = idx - c * 324;
            int r = rem / 18, cc = rem - r * 18;
            int yy = (int)blockIdx.y * 16 + r - 1;
            int xx = (int)blockIdx.x * 16 + cc - 1;
            float v = 0.f;
            if (yy >= 0 && yy < 128 && xx >= 0 && xx < 128)
                v = emb[(size_t)(ci0 + c) * 16384 + yy * 128 + xx];
            tile[c][rem] = v;
        }
        __syncthreads();
#pragma unroll
        for (int c = 0; c < 4; c++) {
            float t[9];
#pragma unroll
            for (int kh = 0; kh < 3; kh++)
#pragma unroll
                for (int kw = 0; kw < 3; kw++)
                    t[kh * 3 + kw] = tile[c][(threadIdx.y + kh) * 18 + threadIdx.x + kw];
            const float* w = ws + (ci0 + c) * 9;
#pragma unroll
            for (int o = 0; o < 16; o++)
#pragma unroll
                for (int k = 0; k < 9; k++)
                    acc[o] = fmaf(w[o * 576 + k], t[k], acc[o]);
        }
    }

    const float a = prelu1[0];
#pragma unroll
    for (int o = 0; o < 16; o++) {
        float y  = acc[o] + en_b[o];
        float sc = bn1_g[o] * rsqrtf(bn1_v[o] + EPS);
        y = (y - bn1_m[o]) * sc + bn1_b[o];
        y = (y >= 0.f) ? y : a * y;
        g_tmp[(((size_t)b * 16 + o) * 128 + gy) * 128 + gx] = y;
    }
}

// ---------------------------------------------------------------------------
// Kernel 2: build f
// ---------------------------------------------------------------------------
__global__ __launch_bounds__(256) void k_build_f(
    const float* __restrict__ dm, const float* __restrict__ de_w,
    const float* __restrict__ de_b, const float* __restrict__ dw_w,
    const float* __restrict__ dw_b)
{
    const int b  = blockIdx.z;
    const int ch = blockIdx.y;
    const int i  = blockIdx.x * 256 + threadIdx.x;
    float out;
    if (ch < 16) {
        const int ph = i >> 6, pw = i & 63;
        float m = -1e30f;
        const float* tb = g_tmp + ((size_t)b * 16 + ch) * 16384;
#pragma unroll
        for (int dy = 0; dy < 3; dy++) {
            int y = 2 * ph - 1 + dy;
            if (y < 0 || y > 127) continue;
#pragma unroll
            for (int dx = 0; dx < 3; dx++) {
                int x = 2 * pw - 1 + dx;
                if (x < 0 || x > 127) continue;
                m = fmaxf(m, tb[y * 128 + x]);
            }
        }
        out = m * dw_w[ch] + dw_b[ch];
    } else {
        const int co = ch - 16;
        float accv = de_b[co];
        const float* dmb = dm + (size_t)b * 128 * NPIX + i;
        const float* w   = de_w + co * 128;
#pragma unroll 8
        for (int c = 0; c < 128; c++)
            accv = fmaf(__ldg(w + c), __ldg(dmb + (size_t)c * NPIX), accv);
        out = accv;
    }
    g_f[((size_t)b * 48 + ch) * NPIX + i] = out;
}

// ---------------------------------------------------------------------------
// Kernel 3: QKV -> split-bf16 planes (+ g_ov = V*p); weights in SMEM
// grid (16, 3, 4), 256 thr
// ---------------------------------------------------------------------------
__global__ __launch_bounds__(256) void k_qkv_t(
    const float* __restrict__ q_w, const float* __restrict__ q_b,
    const float* __restrict__ k_w, const float* __restrict__ k_b,
    const float* __restrict__ v_w, const float* __restrict__ v_b,
    const float* __restrict__ p)
{
    __shared__ float ws[128 * 48];
    __shared__ float bsm[128];
    const int b    = blockIdx.z;
    const int proj = blockIdx.y;
    const int tid  = threadIdx.x;
    const int i    = blockIdx.x * 256 + tid;

    const float* w  = (proj == 0) ? q_w : (proj == 1) ? k_w : v_w;
    const float* bb = (proj == 0) ? q_b : (proj == 1) ? k_b : v_b;
    for (int idx = tid; idx < 128 * 48; idx += 256) ws[idx] = w[idx];
    if (tid < 128) bsm[tid] = bb[tid];
    __syncthreads();

    float fv[48];
#pragma unroll
    for (int k = 0; k < 48; k++)
        fv[k] = g_f[((size_t)b * 48 + k) * NPIX + i];

    if (proj < 2) {
        __nv_bfloat16* hi = ((proj == 0) ? g_qhi : g_khi) + ((size_t)b * NPIX + i) * CATT;
        __nv_bfloat16* lo = ((proj == 0) ? g_qlo : g_klo) + ((size_t)b * NPIX + i) * CATT;
        for (int c8 = 0; c8 < 16; c8++) {
            uint4 hib, lob;
            __nv_bfloat16* hb = (__nv_bfloat16*)&hib;
            __nv_bfloat16* lb = (__nv_bfloat16*)&lob;
#pragma unroll
            for (int cc = 0; cc < 8; cc++) {
                int c = c8 * 8 + cc;
                float accv = bsm[c];
                const float* wr = ws + c * 48;
#pragma unroll
                for (int k = 0; k < 48; k++)
                    accv = fmaf(wr[k], fv[k], accv);
                __nv_bfloat16 h = __float2bfloat16(accv);
                hb[cc] = h;
                lb[cc] = __float2bfloat16(accv - __bfloat162float(h));
            }
            *(uint4*)(hi + c8 * 8) = hib;
            *(uint4*)(lo + c8 * 8) = lob;
        }
    } else {
        const float pv = p[(size_t)b * NPIX + i];
        for (int c = 0; c < 128; c++) {
            float accv = bsm[c];
            const float* wr = ws + c * 48;
#pragma unroll
            for (int k = 0; k < 48; k++)
                accv = fmaf(wr[k], fv[k], accv);
            __nv_bfloat16 h = __float2bfloat16(accv);
            size_t off = ((size_t)b * CATT + c) * NPIX + i;
            g_vhi[off] = h;
            g_vlo[off] = __float2bfloat16(accv - __bfloat162float(h));
            g_ov[off]  = accv * pv;
        }
    }
}

// ---------------------------------------------------------------------------
// Kernel 4: GEMM1 (HMMA, cp.async double-buffered)
// att_hi/lo[i][j] = split(sigmoid(sum_c Q[i][c] K[j][c]))
// grid (32 jt, 32 it, 4), 256 thr, dyn smem 80KB
// ---------------------------------------------------------------------------
__global__ __launch_bounds__(256, 2) void k_gemm1()
{
    extern __shared__ char smem[];
    const uint32_t su = smem_u32(smem);

    const int tid  = threadIdx.x;
    const int lane = tid & 31;
    const int warp = tid >> 5;
    const int wm = (warp & 1) * 64;
    const int wn = (warp >> 1) * 32;
    const int b  = blockIdx.z;
    const int i0 = blockIdx.y * 128;
    const int j0 = blockIdx.x * 128;

    const __nv_bfloat16* Ah = g_qhi + ((size_t)b * NPIX + i0) * CATT;
    const __nv_bfloat16* Al = g_qlo + ((size_t)b * NPIX + i0) * CATT;
    const __nv_bfloat16* Bh = g_khi + ((size_t)b * NPIX + j0) * CATT;
    const __nv_bfloat16* Bl = g_klo + ((size_t)b * NPIX + j0) * CATT;

    float acc[4][4][4];
#pragma unroll
    for (int mi = 0; mi < 4; mi++)
#pragma unroll
        for (int ni = 0; ni < 4; ni++)
#pragma unroll
            for (int q = 0; q < 4; q++) acc[mi][ni][q] = 0.f;

    auto stage = [&](int buf, int c0) {
        uint32_t base = su + buf * 4 * PLANE_B;
#pragma unroll
        for (int t = 0; t < 2; t++) {
            int idx = tid + t * 256;
            int r = idx >> 2, s = (idx & 3) * 8;
            uint32_t so = base + (uint32_t)(r * SPAD + s) * 2;
            size_t go = (size_t)r * CATT + c0 + s;
            cp16(so,               Ah + go);
            cp16(so + PLANE_B,     Al + go);
            cp16(so + 2 * PLANE_B, Bh + go);
            cp16(so + 3 * PLANE_B, Bl + go);
        }
        CP_COMMIT();
    };

    stage(0, 0);
    for (int it = 0; it < 4; it++) {
        if (it < 3) { stage((it + 1) & 1, (it + 1) * 32); CP_WAIT1(); }
        else        { CP_WAIT0(); }
        __syncthreads();
        const uint32_t ub = su + (it & 1) * 4 * PLANE_B;
        const uint32_t uAh = ub, uAl = ub + PLANE_B;
        const uint32_t uBh = ub + 2 * PLANE_B, uBl = ub + 3 * PLANE_B;
#pragma unroll
        for (int ks = 0; ks < 2; ks++) {
            const int k0 = ks * 16;
            const uint32_t aoff =
                (uint32_t)(((wm + (lane & 15)) * SPAD + k0 + ((lane >> 4) << 3)) * 2);
            const uint32_t boff =
                (uint32_t)(((wn + (lane & 7) + ((lane >> 4) << 3)) * SPAD +
                            k0 + (((lane >> 3) & 1) << 3)) * 2);
            uint32_t ah[4][4], al[4][4];
#pragma unroll
            for (int mi = 0; mi < 4; mi++) {
                ldmx4(ah[mi], uAh + aoff + mi * 16 * SPAD * 2);
                ldmx4(al[mi], uAl + aoff + mi * 16 * SPAD * 2);
            }
#pragma unroll
            for (int nj = 0; nj < 2; nj++) {
                uint32_t bh[4], bl[4];
                ldmx4(bh, uBh + boff + nj * 16 * SPAD * 2);
                ldmx4(bl, uBl + boff + nj * 16 * SPAD * 2);
#pragma unroll
                for (int mi = 0; mi < 4; mi++) {
                    mma16816(acc[mi][2 * nj],     ah[mi], bh);
                    mma16816(acc[mi][2 * nj],     al[mi], bh);
                    mma16816(acc[mi][2 * nj],     ah[mi], bl);
                    mma16816(acc[mi][2 * nj + 1], ah[mi], bh + 2);
                    mma16816(acc[mi][2 * nj + 1], al[mi], bh + 2);
                    mma16816(acc[mi][2 * nj + 1], ah[mi], bl + 2);
                }
            }
        }
        __syncthreads();
    }

    // epilogue: sigmoid + hi/lo bf16 store
    __nv_bfloat16* oh = g_atth + ((size_t)b * NPIX + i0) * NPIX + j0;
    __nv_bfloat16* ol = g_attl + ((size_t)b * NPIX + i0) * NPIX + j0;
#pragma unroll
    for (int mi = 0; mi < 4; mi++) {
        int r0 = wm + mi * 16 + (lane >> 2);
#pragma unroll
        for (int ni = 0; ni < 4; ni++) {
            int cc = wn + ni * 8 + 2 * (lane & 3);
            float s[4];
#pragma unroll
            for (int q = 0; q < 4; q++)
                s[q] = __fdividef(1.f, 1.f + __expf(-acc[mi][ni][q]));
            float h0 = __bfloat162float(__float2bfloat16(s[0]));
            float h1 = __bfloat162float(__float2bfloat16(s[1]));
            float h2 = __bfloat162float(__float2bfloat16(s[2]));
            float h3 = __bfloat162float(__float2bfloat16(s[3]));
            *(uint32_t*)(oh + (size_t)r0 * NPIX + cc)       = pk2bf(s[0], s[1]);
            *(uint32_t*)(ol + (size_t)r0 * NPIX + cc)       = pk2bf(s[0] - h0, s[1] - h1);
            *(uint32_t*)(oh + (size_t)(r0 + 8) * NPIX + cc) = pk2bf(s[2], s[3]);
            *(uint32_t*)(ol + (size_t)(r0 + 8) * NPIX + cc) = pk2bf(s[2] - h2, s[3] - h3);
        }
    }
}

// ---------------------------------------------------------------------------
// Kernel 5: GEMM2 (HMMA, split-K over j, cp.async double-buffered)
// g_ov[c][i] += sum_j V[c][j] att[i][j]
// grid (8 jc, 32 it, 4), 256 thr, dyn smem 80KB
// ---------------------------------------------------------------------------
__global__ __launch_bounds__(256, 2) void k_gemm2()
{
    extern __shared__ char smem[];
    const uint32_t su = smem_u32(smem);

    const int tid  = threadIdx.x;
    const int lane = tid & 31;
    const int warp = tid >> 5;
    const int wm = (warp & 1) * 64;     // m = c
    const int wn = (warp >> 1) * 32;    // n = i
    const int b   = blockIdx.z;
    const int i0  = blockIdx.y * 128;
    const int jc0 = blockIdx.x * 512;

    const __nv_bfloat16* Vh = g_vhi + (size_t)b * CATT * NPIX;
    const __nv_bfloat16* Vl = g_vlo + (size_t)b * CATT * NPIX;
    const __nv_bfloat16* Th = g_atth + ((size_t)b * NPIX + i0) * NPIX;
    const __nv_bfloat16* Tl = g_attl + ((size_t)b * NPIX + i0) * NPIX;

    float acc[4][4][4];
#pragma unroll
    for (int mi = 0; mi < 4; mi++)
#pragma unroll
        for (int ni = 0; ni < 4; ni++)
#pragma unroll
            for (int q = 0; q < 4; q++) acc[mi][ni][q] = 0.f;

    auto stage = [&](int buf, int j0) {
        uint32_t base = su + buf * 4 * PLANE_B;
#pragma unroll
        for (int t = 0; t < 2; t++) {
            int idx = tid + t * 256;
            int r = idx >> 2, s = (idx & 3) * 8;
            uint32_t so = base + (uint32_t)(r * SPAD + s) * 2;
            size_t go = (size_t)r * NPIX + j0 + s;
            cp16(so,               Vh + go);
            cp16(so + PLANE_B,     Vl + go);
            cp16(so + 2 * PLANE_B, Th + go);
            cp16(so + 3 * PLANE_B, Tl + go);
        }
        CP_COMMIT();
    };

    stage(0, jc0);
    for (int st = 0; st < 16; st++) {
        if (st < 15) { stage((st + 1) & 1, jc0 + (st + 1) * 32); CP_WAIT1(); }
        else         { CP_WAIT0(); }
        __syncthreads();
        const uint32_t ub = su + (st & 1) * 4 * PLANE_B;
        const uint32_t uAh = ub, uAl = ub + PLANE_B;
        const uint32_t uBh = ub + 2 * PLANE_B, uBl = ub + 3 * PLANE_B;
#pragma unroll
        for (int ks = 0; ks < 2; ks++) {
            const int k0 = ks * 16;
            const uint32_t aoff =
                (uint32_t)(((wm + (lane & 15)) * SPAD + k0 + ((lane >> 4) << 3)) * 2);
            const uint32_t boff =
                (uint32_t)(((wn + (lane & 7) + ((lane >> 4) << 3)) * SPAD +
                            k0 + (((lane >> 3) & 1) << 3)) * 2);
            uint32_t ah[4][4], al[4][4];
#pragma unroll
            for (int mi = 0; mi < 4; mi++) {
                ldmx4(ah[mi], uAh + aoff + mi * 16 * SPAD * 2);
                ldmx4(al[mi], uAl + aoff + mi * 16 * SPAD * 2);
            }
#pragma unroll
            for (int nj = 0; nj < 2; nj++) {
                uint32_t bh[4], bl[4];
                ldmx4(bh, uBh + boff + nj * 16 * SPAD * 2);
                ldmx4(bl, uBl + boff + nj * 16 * SPAD * 2);
#pragma unroll
                for (int mi = 0; mi < 4; mi++) {
                    mma16816(acc[mi][2 * nj],     ah[mi], bh);
                    mma16816(acc[mi][2 * nj],     al[mi], bh);
                    mma16816(acc[mi][2 * nj],     ah[mi], bl);
                    mma16816(acc[mi][2 * nj + 1], ah[mi], bh + 2);
                    mma16816(acc[mi][2 * nj + 1], al[mi], bh + 2);
                    mma16816(acc[mi][2 * nj + 1], ah[mi], bl + 2);
                }
            }
        }
        __syncthreads();
    }

    // epilogue: atomicAdd into g_ov
    float* ob = g_ov + ((size_t)b * CATT) * NPIX + i0;
#pragma unroll
    for (int mi = 0; mi < 4; mi++) {
        int c0 = wm + mi * 16 + (lane >> 2);
#pragma unroll
        for (int ni = 0; ni < 4; ni++) {
            int ii = wn + ni * 8 + 2 * (lane & 3);
            atomicAdd(ob + (size_t)c0 * NPIX + ii,           acc[mi][ni][0]);
            atomicAdd(ob + (size_t)c0 * NPIX + ii + 1,       acc[mi][ni][1]);
            atomicAdd(ob + (size_t)(c0 + 8) * NPIX + ii,     acc[mi][ni][2]);
            atomicAdd(ob + (size_t)(c0 + 8) * NPIX + ii + 1, acc[mi][ni][3]);
        }
    }
}

// ---------------------------------------------------------------------------
// Kernel 6: bottleneck 1x1 + BN + PReLU -> out
// ---------------------------------------------------------------------------
__global__ __launch_bounds__(256) void k_bt(
    const float* __restrict__ bt_w, const float* __restrict__ bt_b,
    const float* __restrict__ bn2_g, const float* __restrict__ bn2_b,
    const float* __restrict__ bn2_m, const float* __restrict__ bn2_v,
    const float* __restrict__ prelu2, float* __restrict__ out)
{
    __shared__ float ovs[128][64];
    const int b  = blockIdx.y;
    const int i0 = blockIdx.x * 64;
    const int tid = threadIdx.x;

    for (int idx = tid; idx < 128 * 64; idx += 256) {
        int c = idx >> 6, ii = idx & 63;
        ovs[c][ii] = g_ov[((size_t)b * CATT + c) * NPIX + i0 + ii];
    }
    __syncthreads();

    const int il = tid & 63, og = tid >> 6;
    float accs[16];
#pragma unroll
    for (int n = 0; n < 16; n++) accs[n] = 0.f;

    for (int c = 0; c < 128; c++) {
        float v = ovs[c][il];
#pragma unroll
        for (int n = 0; n < 16; n++)
            accs[n] = fmaf(__ldg(bt_w + (og * 16 + n) * 128 + c), v, accs[n]);
    }

    const float a = prelu2[0];
#pragma unroll
    for (int n = 0; n < 16; n++) {
        int o = og * 16 + n;
        float y  = accs[n] + bt_b[o];
        float sc = bn2_g[o] * rsqrtf(bn2_v[o] + EPS);
        y = (y - bn2_m[o]) * sc + bn2_b[o];
        y = (y >= 0.f) ? y : a * y;
        out[((size_t)b * 64 + o) * NPIX + i0 + il] = y;
    }
}

// ---------------------------------------------------------------------------
extern "C" void kernel_launch(void* const* d_in, const int* in_sizes, int n_in,
                              void* d_out, int out_size)
{
    const float* em     = (const float*)d_in[0];
    const float* dm     = (const float*)d_in[1];
    const float* p      = (const float*)d_in[2];
    const float* en_w   = (const float*)d_in[3];
    const float* en_b   = (const float*)d_in[4];
    const float* bn1_g  = (const float*)d_in[5];
    const float* bn1_b  = (const float*)d_in[6];
    const float* bn1_m  = (const float*)d_in[7];
    const float* bn1_v  = (const float*)d_in[8];
    const float* prelu1 = (const float*)d_in[9];
    const float* dw_w   = (const float*)d_in[10];
    const float* dw_b   = (const float*)d_in[11];
    const float* de_w   = (const float*)d_in[12];
    const float* de_b   = (const float*)d_in[13];
    const float* q_w    = (const float*)d_in[14];
    const float* q_b    = (const float*)d_in[15];
    const float* k_w    = (const float*)d_in[16];
    const float* k_b    = (const float*)d_in[17];
    const float* v_w    = (const float*)d_in[18];
    const float* v_b    = (const float*)d_in[19];
    const float* bt_w   = (const float*)d_in[20];
    const float* bt_b   = (const float*)d_in[21];
    const float* bn2_g  = (const float*)d_in[22];
    const float* bn2_b  = (const float*)d_in[23];
    const float* bn2_m  = (const float*)d_in[24];
    const float* bn2_v  = (const float*)d_in[25];
    const float* prelu2 = (const float*)d_in[26];

    cudaFuncSetAttribute(k_gemm1, cudaFuncAttributeMaxDynamicSharedMemorySize, G_SMEM);
    cudaFuncSetAttribute(k_gemm2, cudaFuncAttributeMaxDynamicSharedMemorySize, G_SMEM);

    k_conv3  <<<dim3(8, 8, 4),   dim3(16, 16)>>>(em, en_w, en_b, bn1_g, bn1_b,
                                                 bn1_m, bn1_v, prelu1);
    k_build_f<<<dim3(16, 48, 4), 256>>>(dm, de_w, de_b, dw_w, dw_b);
    k_qkv_t  <<<dim3(16, 3, 4),  256>>>(q_w, q_b, k_w, k_b, v_w, v_b, p);
    k_gemm1  <<<dim3(32, 32, 4), 256, G_SMEM>>>();
    k_gemm2  <<<dim3(8, 32, 4),  256, G_SMEM>>>();
    k_bt     <<<dim3(64, 4),     256>>>(bt_w, bt_b, bn2_g, bn2_b, bn2_m, bn2_v,
                                        prelu2, (float*)d_out);
}

// round 5
// speedup vs baseline: 4.7497x; 1.6207x over previous
#include <cuda_runtime.h>
#include <cuda_bf16.h>
#include <cuda_fp16.h>
#include <cstdint>

#define BATCH 4
#define NPIX  4096
#define CATT  128
#define EPS   1e-5f

// ---------------- device scratch ------------------------------------------
__device__ float g_tmp[BATCH * 16 * 128 * 128];
__device__ float g_f  [BATCH * 48 * NPIX];
__device__ __half g_q [(size_t)BATCH * NPIX * CATT];    // [b][i][c]
__device__ __half g_k [(size_t)BATCH * NPIX * CATT];    // [b][j][c]
__device__ __half g_v [(size_t)BATCH * CATT * NPIX];    // [b][c][j]
__device__ __half g_att[(size_t)BATCH * NPIX * NPIX];   // fp16 att (134 MB)
__device__ float g_ov [BATCH * CATT * NPIX];            // V*p + self_v

// ---------------- helpers --------------------------------------------------
__device__ __forceinline__ uint32_t smem_u32(const void* smem_ptr) {
    uint32_t addr;
    asm("{ .reg .u64 tmp; cvta.to.shared.u64 tmp, %1; cvt.u32.u64 %0, tmp; }"
        : "=r"(addr) : "l"(smem_ptr));
    return addr;
}
__device__ __forceinline__ void ldmx4(uint32_t* r, uint32_t addr) {
    asm volatile("ldmatrix.sync.aligned.m8n8.x4.shared.b16 {%0,%1,%2,%3}, [%4];"
        : "=r"(r[0]), "=r"(r[1]), "=r"(r[2]), "=r"(r[3]) : "r"(addr));
}
__device__ __forceinline__ void mma16816(float* c, const uint32_t* a,
                                         const uint32_t* b) {
    asm volatile(
        "mma.sync.aligned.m16n8k16.row.col.f32.f16.f16.f32 "
        "{%0,%1,%2,%3}, {%4,%5,%6,%7}, {%8,%9}, {%0,%1,%2,%3};"
        : "+f"(c[0]), "+f"(c[1]), "+f"(c[2]), "+f"(c[3])
        : "r"(a[0]), "r"(a[1]), "r"(a[2]), "r"(a[3]), "r"(b[0]), "r"(b[1]));
}
__device__ __forceinline__ void cp16(uint32_t dst, const void* src) {
    asm volatile("cp.async.ca.shared.global [%0], [%1], 16;"
                 :: "r"(dst), "l"(src) : "memory");
}
#define CP_COMMIT() asm volatile("cp.async.commit_group;" ::: "memory")
#define CP_WAIT1()  asm volatile("cp.async.wait_group 1;" ::: "memory")
#define CP_WAIT0()  asm volatile("cp.async.wait_group 0;" ::: "memory")

#define ST128 136   // half-stride for 128-wide rows (272B, ldmatrix conflict-free)
#define ST64  72    // half-stride for 64-wide rows (144B)

#define G1_PLANE (128 * ST128 * 2)            // 34816 B
#define G1_SMEM  (2 * G1_PLANE)               // A + B (single stage, K=128)
#define G2_PLANE (128 * ST64 * 2)             // 18432 B
#define G2_BUF   (2 * G2_PLANE)               // A + B per stage
#define G2_SMEM  (2 * G2_BUF)                 // double buffered

__device__ __forceinline__ uint32_t pk2h(float a, float b) {
    __half2 h = __floats2half2_rn(a, b);
    return *(uint32_t*)&h;
}

// ---------------------------------------------------------------------------
// Kernel 1: conv3x3(em) + BN + PReLU  -> g_tmp  (4 channels per sync round)
// ---------------------------------------------------------------------------
__global__ __launch_bounds__(256) void k_conv3(
    const float* __restrict__ em, const float* __restrict__ en_w,
    const float* __restrict__ en_b, const float* __restrict__ bn1_g,
    const float* __restrict__ bn1_b, const float* __restrict__ bn1_m,
    const float* __restrict__ bn1_v, const float* __restrict__ prelu1)
{
    __shared__ float ws[16 * 64 * 9];
    __shared__ float tile[4][18 * 18];
    const int tid = threadIdx.y * 16 + threadIdx.x;
    for (int idx = tid; idx < 16 * 64 * 9; idx += 256) ws[idx] = en_w[idx];

    const int b  = blockIdx.z;
    const int gx = blockIdx.x * 16 + threadIdx.x;
    const int gy = blockIdx.y * 16 + threadIdx.y;

    float acc[16];
#pragma unroll
    for (int o = 0; o < 16; o++) acc[o] = 0.f;
    const float* emb = em + (size_t)b * 64 * 128 * 128;

    for (int ci0 = 0; ci0 < 64; ci0 += 4) {
        __syncthreads();
        for (int idx = tid; idx < 4 * 324; idx += 256) {
            int c = idx / 324, rem = idx - c * 324;
            int r = rem / 18, cc = rem - r * 18;
            int yy = (int)blockIdx.y * 16 + r - 1;
            int xx = (int)blockIdx.x * 16 + cc - 1;
            float v = 0.f;
            if (yy >= 0 && yy < 128 && xx >= 0 && xx < 128)
                v = emb[(size_t)(ci0 + c) * 16384 + yy * 128 + xx];
            tile[c][rem] = v;
        }
        __syncthreads();
#pragma unroll
        for (int c = 0; c < 4; c++) {
            float t[9];
#pragma unroll
            for (int kh = 0; kh < 3; kh++)
#pragma unroll
                for (int kw = 0; kw < 3; kw++)
                    t[kh * 3 + kw] = tile[c][(threadIdx.y + kh) * 18 + threadIdx.x + kw];
            const float* w = ws + (ci0 + c) * 9;
#pragma unroll
            for (int o = 0; o < 16; o++)
#pragma unroll
                for (int k = 0; k < 9; k++)
                    acc[o] = fmaf(w[o * 576 + k], t[k], acc[o]);
        }
    }

    const float a = prelu1[0];
#pragma unroll
    for (int o = 0; o < 16; o++) {
        float y  = acc[o] + en_b[o];
        float sc = bn1_g[o] * rsqrtf(bn1_v[o] + EPS);
        y = (y - bn1_m[o]) * sc + bn1_b[o];
        y = (y >= 0.f) ? y : a * y;
        g_tmp[(((size_t)b * 16 + o) * 128 + gy) * 128 + gx] = y;
    }
}

// ---------------------------------------------------------------------------
// Kernel 2: build f
// ---------------------------------------------------------------------------
__global__ __launch_bounds__(256) void k_build_f(
    const float* __restrict__ dm, const float* __restrict__ de_w,
    const float* __restrict__ de_b, const float* __restrict__ dw_w,
    const float* __restrict__ dw_b)
{
    const int b  = blockIdx.z;
    const int ch = blockIdx.y;
    const int i  = blockIdx.x * 256 + threadIdx.x;
    float out;
    if (ch < 16) {
        const int ph = i >> 6, pw = i & 63;
        float m = -1e30f;
        const float* tb = g_tmp + ((size_t)b * 16 + ch) * 16384;
#pragma unroll
        for (int dy = 0; dy < 3; dy++) {
            int y = 2 * ph - 1 + dy;
            if (y < 0 || y > 127) continue;
#pragma unroll
            for (int dx = 0; dx < 3; dx++) {
                int x = 2 * pw - 1 + dx;
                if (x < 0 || x > 127) continue;
                m = fmaxf(m, tb[y * 128 + x]);
            }
        }
        out = m * dw_w[ch] + dw_b[ch];
    } else {
        const int co = ch - 16;
        float accv = de_b[co];
        const float* dmb = dm + (size_t)b * 128 * NPIX + i;
        const float* w   = de_w + co * 128;
#pragma unroll 8
        for (int c = 0; c < 128; c++)
            accv = fmaf(__ldg(w + c), __ldg(dmb + (size_t)c * NPIX), accv);
        out = accv;
    }
    g_f[((size_t)b * 48 + ch) * NPIX + i] = out;
}

// ---------------------------------------------------------------------------
// Kernel 3: QKV -> fp16 planes (+ g_ov = V*p); weights in SMEM
// grid (16, 3, 4), 256 thr
// ---------------------------------------------------------------------------
__global__ __launch_bounds__(256) void k_qkv_t(
    const float* __restrict__ q_w, const float* __restrict__ q_b,
    const float* __restrict__ k_w, const float* __restrict__ k_b,
    const float* __restrict__ v_w, const float* __restrict__ v_b,
    const float* __restrict__ p)
{
    __shared__ float ws[128 * 48];
    __shared__ float bsm[128];
    const int b    = blockIdx.z;
    const int proj = blockIdx.y;
    const int tid  = threadIdx.x;
    const int i    = blockIdx.x * 256 + tid;

    const float* w  = (proj == 0) ? q_w : (proj == 1) ? k_w : v_w;
    const float* bb = (proj == 0) ? q_b : (proj == 1) ? k_b : v_b;
    for (int idx = tid; idx < 128 * 48; idx += 256) ws[idx] = w[idx];
    if (tid < 128) bsm[tid] = bb[tid];
    __syncthreads();

    float fv[48];
#pragma unroll
    for (int k = 0; k < 48; k++)
        fv[k] = g_f[((size_t)b * 48 + k) * NPIX + i];

    if (proj < 2) {
        __half* dst = ((proj == 0) ? g_q : g_k) + ((size_t)b * NPIX + i) * CATT;
        for (int c8 = 0; c8 < 16; c8++) {
            uint4 pkt;
            __half* hb = (__half*)&pkt;
#pragma unroll
            for (int cc = 0; cc < 8; cc++) {
                int c = c8 * 8 + cc;
                float accv = bsm[c];
                const float* wr = ws + c * 48;
#pragma unroll
                for (int k = 0; k < 48; k++)
                    accv = fmaf(wr[k], fv[k], accv);
                hb[cc] = __float2half_rn(accv);
            }
            *(uint4*)(dst + c8 * 8) = pkt;
        }
    } else {
        const float pv = p[(size_t)b * NPIX + i];
        for (int c = 0; c < 128; c++) {
            float accv = bsm[c];
            const float* wr = ws + c * 48;
#pragma unroll
            for (int k = 0; k < 48; k++)
                accv = fmaf(wr[k], fv[k], accv);
            size_t off = ((size_t)b * CATT + c) * NPIX + i;
            g_v[off]  = __float2half_rn(accv);
            g_ov[off] = accv * pv;
        }
    }
}

// ---------------------------------------------------------------------------
// Kernel 4: GEMM1 (fp16 HMMA, single pass): att[i][j] = sigmoid(Q·K^T)
// 128x128 tile, full K=128 staged once. grid (32 jt, 32 it, 4), 256 thr.
// ---------------------------------------------------------------------------
__global__ __launch_bounds__(256, 2) void k_gemm1()
{
    extern __shared__ char smem[];
    const uint32_t su = smem_u32(smem);
    const uint32_t uA = su, uB = su + G1_PLANE;

    const int tid  = threadIdx.x;
    const int lane = tid & 31;
    const int warp = tid >> 5;
    const int wm = (warp & 1) * 64;
    const int wn = (warp >> 1) * 32;
    const int b  = blockIdx.z;
    const int i0 = blockIdx.y * 128;
    const int j0 = blockIdx.x * 128;

    const __half* A = g_q + ((size_t)b * NPIX + i0) * CATT;
    const __half* B = g_k + ((size_t)b * NPIX + j0) * CATT;

    // stage full 128x128 A and B tiles
#pragma unroll
    for (int t = 0; t < 8; t++) {
        int idx = tid + t * 256;        // 0..2047
        int r = idx >> 4, s = (idx & 15) * 8;
        uint32_t so = (uint32_t)(r * ST128 + s) * 2;
        cp16(uA + so, A + (size_t)r * CATT + s);
        cp16(uB + so, B + (size_t)r * CATT + s);
    }
    CP_COMMIT();
    CP_WAIT0();
    __syncthreads();

    float acc[4][4][4];
#pragma unroll
    for (int mi = 0; mi < 4; mi++)
#pragma unroll
        for (int ni = 0; ni < 4; ni++)
#pragma unroll
            for (int q = 0; q < 4; q++) acc[mi][ni][q] = 0.f;

#pragma unroll
    for (int kt = 0; kt < 8; kt++) {
        const int k0 = kt * 16;
        const uint32_t aoff =
            (uint32_t)(((wm + (lane & 15)) * ST128 + k0 + ((lane >> 4) << 3)) * 2);
        const uint32_t boff =
            (uint32_t)(((wn + (lane & 7) + ((lane >> 4) << 3)) * ST128 +
                        k0 + (((lane >> 3) & 1) << 3)) * 2);
        uint32_t a[4][4];
#pragma unroll
        for (int mi = 0; mi < 4; mi++)
            ldmx4(a[mi], uA + aoff + mi * 16 * ST128 * 2);
#pragma unroll
        for (int nj = 0; nj < 2; nj++) {
            uint32_t bfr[4];
            ldmx4(bfr, uB + boff + nj * 16 * ST128 * 2);
#pragma unroll
            for (int mi = 0; mi < 4; mi++) {
                mma16816(acc[mi][2 * nj],     a[mi], bfr);
                mma16816(acc[mi][2 * nj + 1], a[mi], bfr + 2);
            }
        }
    }

    // epilogue: sigmoid + fp16 store
    __half* oh = g_att + ((size_t)b * NPIX + i0) * NPIX + j0;
#pragma unroll
    for (int mi = 0; mi < 4; mi++) {
        int r0 = wm + mi * 16 + (lane >> 2);
#pragma unroll
        for (int ni = 0; ni < 4; ni++) {
            int cc = wn + ni * 8 + 2 * (lane & 3);
            float s[4];
#pragma unroll
            for (int q = 0; q < 4; q++)
                s[q] = __fdividef(1.f, 1.f + __expf(-acc[mi][ni][q]));
            *(uint32_t*)(oh + (size_t)r0 * NPIX + cc)       = pk2h(s[0], s[1]);
            *(uint32_t*)(oh + (size_t)(r0 + 8) * NPIX + cc) = pk2h(s[2], s[3]);
        }
    }
}

// ---------------------------------------------------------------------------
// Kernel 5: GEMM2 (fp16 HMMA, split-K=2 over j, double-buffered)
// g_ov[c][i] += sum_j V[c][j] att[i][j]
// grid (2 jc, 32 it, 4), 256 thr
// ---------------------------------------------------------------------------
__global__ __launch_bounds__(256, 2) void k_gemm2()
{
    extern __shared__ char smem[];
    const uint32_t su = smem_u32(smem);

    const int tid  = threadIdx.x;
    const int lane = tid & 31;
    const int warp = tid >> 5;
    const int wm = (warp & 1) * 64;     // m = c
    const int wn = (warp >> 1) * 32;    // n = i
    const int b   = blockIdx.z;
    const int i0  = blockIdx.y * 128;
    const int jc0 = blockIdx.x * 2048;

    const __half* V = g_v + (size_t)b * CATT * NPIX;
    const __half* T = g_att + ((size_t)b * NPIX + i0) * NPIX;

    float acc[4][4][4];
#pragma unroll
    for (int mi = 0; mi < 4; mi++)
#pragma unroll
        for (int ni = 0; ni < 4; ni++)
#pragma unroll
            for (int q = 0; q < 4; q++) acc[mi][ni][q] = 0.f;

    auto stage = [&](int buf, int j0) {
        uint32_t base = su + buf * G2_BUF;
#pragma unroll
        for (int t = 0; t < 4; t++) {
            int idx = tid + t * 256;      // 0..1023
            int r = idx >> 3, s = (idx & 7) * 8;
            uint32_t so = base + (uint32_t)(r * ST64 + s) * 2;
            cp16(so,            V + (size_t)r * NPIX + j0 + s);
            cp16(so + G2_PLANE, T + (size_t)r * NPIX + j0 + s);
        }
        CP_COMMIT();
    };

    stage(0, jc0);
    for (int st = 0; st < 32; st++) {
        if (st < 31) { stage((st + 1) & 1, jc0 + (st + 1) * 64); CP_WAIT1(); }
        else         { CP_WAIT0(); }
        __syncthreads();
        const uint32_t ub = su + (st & 1) * G2_BUF;
        const uint32_t uA = ub, uB = ub + G2_PLANE;
#pragma unroll
        for (int kt = 0; kt < 4; kt++) {
            const int k0 = kt * 16;
            const uint32_t aoff =
                (uint32_t)(((wm + (lane & 15)) * ST64 + k0 + ((lane >> 4) << 3)) * 2);
            const uint32_t boff =
                (uint32_t)(((wn + (lane & 7) + ((lane >> 4) << 3)) * ST64 +
                            k0 + (((lane >> 3) & 1) << 3)) * 2);
            uint32_t a[4][4];
#pragma unroll
            for (int mi = 0; mi < 4; mi++)
                ldmx4(a[mi], uA + aoff + mi * 16 * ST64 * 2);
#pragma unroll
            for (int nj = 0; nj < 2; nj++) {
                uint32_t bfr[4];
                ldmx4(bfr, uB + boff + nj * 16 * ST64 * 2);
#pragma unroll
                for (int mi = 0; mi < 4; mi++) {
                    mma16816(acc[mi][2 * nj],     a[mi], bfr);
                    mma16816(acc[mi][2 * nj + 1], a[mi], bfr + 2);
                }
            }
        }
        __syncthreads();
    }

    // epilogue: atomicAdd into g_ov
    float* ob = g_ov + ((size_t)b * CATT) * NPIX + i0;
#pragma unroll
    for (int mi = 0; mi < 4; mi++) {
        int c0 = wm + mi * 16 + (lane >> 2);
#pragma unroll
        for (int ni = 0; ni < 4; ni++) {
            int ii = wn + ni * 8 + 2 * (lane & 3);
            atomicAdd(ob + (size_t)c0 * NPIX + ii,           acc[mi][ni][0]);
            atomicAdd(ob + (size_t)c0 * NPIX + ii + 1,       acc[mi][ni][1]);
            atomicAdd(ob + (size_t)(c0 + 8) * NPIX + ii,     acc[mi][ni][2]);
            atomicAdd(ob + (size_t)(c0 + 8) * NPIX + ii + 1, acc[mi][ni][3]);
        }
    }
}

// ---------------------------------------------------------------------------
// Kernel 6: bottleneck 1x1 + BN + PReLU -> out
// ---------------------------------------------------------------------------
__global__ __launch_bounds__(256) void k_bt(
    const float* __restrict__ bt_w, const float* __restrict__ bt_b,
    const float* __restrict__ bn2_g, const float* __restrict__ bn2_b,
    const float* __restrict__ bn2_m, const float* __restrict__ bn2_v,
    const float* __restrict__ prelu2, float* __restrict__ out)
{
    __shared__ float ovs[128][64];
    const int b  = blockIdx.y;
    const int i0 = blockIdx.x * 64;
    const int tid = threadIdx.x;

    for (int idx = tid; idx < 128 * 64; idx += 256) {
        int c = idx >> 6, ii = idx & 63;
        ovs[c][ii] = g_ov[((size_t)b * CATT + c) * NPIX + i0 + ii];
    }
    __syncthreads();

    const int il = tid & 63, og = tid >> 6;
    float accs[16];
#pragma unroll
    for (int n = 0; n < 16; n++) accs[n] = 0.f;

    for (int c = 0; c < 128; c++) {
        float v = ovs[c][il];
#pragma unroll
        for (int n = 0; n < 16; n++)
            accs[n] = fmaf(__ldg(bt_w + (og * 16 + n) * 128 + c), v, accs[n]);
    }

    const float a = prelu2[0];
#pragma unroll
    for (int n = 0; n < 16; n++) {
        int o = og * 16 + n;
        float y  = accs[n] + bt_b[o];
        float sc = bn2_g[o] * rsqrtf(bn2_v[o] + EPS);
        y = (y - bn2_m[o]) * sc + bn2_b[o];
        y = (y >= 0.f) ? y : a * y;
        out[((size_t)b * 64 + o) * NPIX + i0 + il] = y;
    }
}

// ---------------------------------------------------------------------------
extern "C" void kernel_launch(void* const* d_in, const int* in_sizes, int n_in,
                              void* d_out, int out_size)
{
    const float* em     = (const float*)d_in[0];
    const float* dm     = (const float*)d_in[1];
    const float* p      = (const float*)d_in[2];
    const float* en_w   = (const float*)d_in[3];
    const float* en_b   = (const float*)d_in[4];
    const float* bn1_g  = (const float*)d_in[5];
    const float* bn1_b  = (const float*)d_in[6];
    const float* bn1_m  = (const float*)d_in[7];
    const float* bn1_v  = (const float*)d_in[8];
    const float* prelu1 = (const float*)d_in[9];
    const float* dw_w   = (const float*)d_in[10];
    const float* dw_b   = (const float*)d_in[11];
    const float* de_w   = (const float*)d_in[12];
    const float* de_b   = (const float*)d_in[13];
    const float* q_w    = (const float*)d_in[14];
    const float* q_b    = (const float*)d_in[15];
    const float* k_w    = (const float*)d_in[16];
    const float* k_b    = (const float*)d_in[17];
    const float* v_w    = (const float*)d_in[18];
    const float* v_b    = (const float*)d_in[19];
    const float* bt_w   = (const float*)d_in[20];
    const float* bt_b   = (const float*)d_in[21];
    const float* bn2_g  = (const float*)d_in[22];
    const float* bn2_b  = (const float*)d_in[23];
    const float* bn2_m  = (const float*)d_in[24];
    const float* bn2_v  = (const float*)d_in[25];
    const float* prelu2 = (const float*)d_in[26];

    cudaFuncSetAttribute(k_gemm1, cudaFuncAttributeMaxDynamicSharedMemorySize, G1_SMEM);
    cudaFuncSetAttribute(k_gemm2, cudaFuncAttributeMaxDynamicSharedMemorySize, G2_SMEM);

    k_conv3  <<<dim3(8, 8, 4),   dim3(16, 16)>>>(em, en_w, en_b, bn1_g, bn1_b,
                                                 bn1_m, bn1_v, prelu1);
    k_build_f<<<dim3(16, 48, 4), 256>>>(dm, de_w, de_b, dw_w, dw_b);
    k_qkv_t  <<<dim3(16, 3, 4),  256>>>(q_w, q_b, k_w, k_b, v_w, v_b, p);
    k_gemm1  <<<dim3(32, 32, 4), 256, G1_SMEM>>>();
    k_gemm2  <<<dim3(2, 32, 4),  256, G2_SMEM>>>();
    k_bt     <<<dim3(64, 4),     256>>>(bt_w, bt_b, bn2_g, bn2_b, bn2_m, bn2_v,
                                        prelu2, (float*)d_out);
}